// round 2
// baseline (speedup 1.0000x reference)
#include <cuda_runtime.h>
#include <math.h>

#define BT      4096
#define KK      64
#define DD      256
#define PP      4
#define KPP     16
#define ROWS    16      // rows per kernel-B CTA
#define THREADS 256
#define COLS    1024    // P*D

typedef unsigned long long ULL;

// 16.8 MB scratch for u, packed as row-pairs:
// layout: [group(=16-row block)][p][r2(=rowpair 0..7)][i(0..255)] as float2
__device__ __align__(16) float u_scratch[(size_t)BT * COLS];

__device__ __forceinline__ void fma2(ULL &acc, ULL a, ULL b) {
    asm("fma.rn.f32x2 %0, %1, %2, %0;" : "+l"(acc) : "l"(a), "l"(b));
}
__device__ __forceinline__ ULL pack2(float lo, float hi) {
    ULL r; asm("mov.b64 %0, {%1, %2};" : "=l"(r) : "f"(lo), "f"(hi)); return r;
}
__device__ __forceinline__ void unpack2(ULL a, float &lo, float &hi) {
    asm("mov.b64 {%0, %1}, %2;" : "=f"(lo), "=f"(hi) : "l"(a));
}
__device__ __forceinline__ ULL mul2(ULL a, ULL b) {
    ULL r; asm("mul.rn.f32x2 %0, %1, %2;" : "=l"(r) : "l"(a), "l"(b)); return r;
}

// ===================== Kernel A: weighted segment-sum (HBM stream) ==========
// grid 2048: CTA = one row PAIR. thread = (part p0, float4 chunk d4).
__global__ __launch_bounds__(256)
void fs_phase1(const float* __restrict__ E_S, const float* __restrict__ W,
               const int* __restrict__ part_idx)
{
    __shared__ float w_s[2 * KK];
    __shared__ float winv_s[2 * PP];
    __shared__ int   pidx_s[KK];

    const int tid = threadIdx.x;
    const int bx  = blockIdx.x;
    const int row0 = bx * 2;

    if (tid < KK)  pidx_s[tid] = part_idx[tid];
    if (tid < 2 * KK) w_s[tid] = W[(size_t)row0 * KK + tid];
    __syncthreads();
    if (tid < 2 * PP) {
        int r = tid >> 2, p = tid & 3;
        float s = 0.f;
#pragma unroll
        for (int kp = 0; kp < KPP; kp++) s += w_s[r * KK + pidx_s[p * KPP + kp]];
        winv_s[tid] = 1.0f / (s + 1e-6f);
    }
    __syncthreads();

    const int p0 = tid >> 6;
    const int d4 = tid & 63;
    const float4* Ea = (const float4*)(E_S + (size_t)row0 * KK * DD);
    const float4* Eb = Ea + (KK * DD / 4);

    float4 aa = make_float4(0.f,0.f,0.f,0.f);
    float4 ab = make_float4(0.f,0.f,0.f,0.f);
#pragma unroll
    for (int kp = 0; kp < KPP; kp++) {
        const int k  = pidx_s[p0 * KPP + kp];
        const float wa = w_s[k];
        const float wb = w_s[KK + k];
        const float4 ea = Ea[k * 64 + d4];
        const float4 eb = Eb[k * 64 + d4];
        aa.x = fmaf(wa, ea.x, aa.x); aa.y = fmaf(wa, ea.y, aa.y);
        aa.z = fmaf(wa, ea.z, aa.z); aa.w = fmaf(wa, ea.w, aa.w);
        ab.x = fmaf(wb, eb.x, ab.x); ab.y = fmaf(wb, eb.y, ab.y);
        ab.z = fmaf(wb, eb.z, ab.z); ab.w = fmaf(wb, eb.w, ab.w);
    }
    const float iva = winv_s[p0];
    const float ivb = winv_s[PP + p0];

    // row-pair interleave: float2(row_even, row_odd) per column
    float4 s0 = make_float4(aa.x * iva, ab.x * ivb, aa.y * iva, ab.y * ivb);
    float4 s1 = make_float4(aa.z * iva, ab.z * ivb, aa.w * iva, ab.w * ivb);

    const size_t group = bx >> 3;        // 16-row block
    const int    r2g   = bx & 7;         // rowpair within block
    float4* out4 = ((float4*)u_scratch) + group * 4096 + (size_t)(p0 * 8 + r2g) * 128 + d4 * 2;
    out4[0] = s0;
    out4[1] = s1;
}

// ===================== Kernel B: GEMMs + gate + LN (FFMA2) ==================
// smem: ULL u_ull[4][8][256] (64KB) | float alpha_s[16*4] | float red_s[16*8*2]
#define SMEMB_BYTES (8192 * 8 + (64 + 256) * 4)

__global__ __launch_bounds__(THREADS, 2)
void fs_phase2(const float* __restrict__ part_W, const float* __restrict__ part_b,
               const float* __restrict__ v, const float* __restrict__ c,
               const float* __restrict__ ln_g, const float* __restrict__ ln_b,
               const float* __restrict__ proj_W, const float* __restrict__ proj_b,
               const float* __restrict__ out_g, const float* __restrict__ out_b,
               float* __restrict__ out)
{
    extern __shared__ ULL u_ull[];                 // [P][8][256] packed row-pairs
    float* alpha_s = (float*)(u_ull + 8192);       // [16][4]
    float* red_s   = alpha_s + 64;                 // [16][8][2]

    const int tid = threadIdx.x;
    const int bt0 = blockIdx.x * ROWS;

    // ---- stage u tile (L2-hot) into smem, identity copy (already packed) ----
    {
        const float4* gsrc = ((const float4*)u_scratch) + (size_t)blockIdx.x * 4096;
        float4* u4s = (float4*)u_ull;
#pragma unroll
        for (int n = 0; n < 16; n++) u4s[tid + n * 256] = gsrc[tid + n * 256];
    }
    __syncthreads();

    // ---- 2a: per-part linear, FFMA2 on row-pairs, 1 out-col per thread ----
#pragma unroll 1
    for (int p = 0; p < PP; p++) {
        const float4* wrow = (const float4*)(part_W + (size_t)(p * DD + tid) * DD);
        const float bias = part_b[p * DD + tid];
        ULL acc[8];
#pragma unroll
        for (int r2 = 0; r2 < 8; r2++) acc[r2] = pack2(bias, bias);

        for (int i4 = 0; i4 < 64; i4++) {
            const float4 w4 = wrow[i4];
            const ULL w0 = pack2(w4.x, w4.x);
            const ULL w1 = pack2(w4.y, w4.y);
            const ULL w2 = pack2(w4.z, w4.z);
            const ULL w3 = pack2(w4.w, w4.w);
#pragma unroll
            for (int r2 = 0; r2 < 8; r2++) {
                const ULL* up = u_ull + (p * 8 + r2) * 256 + i4 * 4;
                const ulonglong2 ua = *(const ulonglong2*)(up);
                const ulonglong2 ub = *(const ulonglong2*)(up + 2);
                fma2(acc[r2], ua.x, w0);
                fma2(acc[r2], ua.y, w1);
                fma2(acc[r2], ub.x, w2);
                fma2(acc[r2], ub.y, w3);
            }
        }
        __syncthreads();
#pragma unroll
        for (int r2 = 0; r2 < 8; r2++) u_ull[(p * 8 + r2) * 256 + tid] = acc[r2];
        __syncthreads();
    }

    // ---- 2b: LN stats + sigmoid gate per (row, part); one warp per pair ----
    {
        const int wid = tid >> 5, lane = tid & 31;
        const float* uh = (const float*)u_ull;
#pragma unroll 1
        for (int j = 0; j < 8; j++) {
            const int pair = wid * 8 + j;
            const int r = pair >> 2, p = pair & 3;
            const int base = ((p * 8 + (r >> 1)) * 256) * 2 + (r & 1);
            float s1 = 0.f, s2 = 0.f, s3 = 0.f, s4 = 0.f, s5 = 0.f;
#pragma unroll
            for (int i = 0; i < DD / 32; i++) {
                const int col = lane + i * 32;
                const float x  = uh[base + col * 2];
                const float vv = v[p * DD + col];
                const float gv = ln_g[p * DD + col] * vv;
                const float bv = ln_b[p * DD + col] * vv;
                s1 += x; s2 += x * x; s3 += x * gv; s4 += gv; s5 += bv;
            }
#pragma unroll
            for (int off = 16; off; off >>= 1) {
                s1 += __shfl_xor_sync(0xffffffffu, s1, off);
                s2 += __shfl_xor_sync(0xffffffffu, s2, off);
                s3 += __shfl_xor_sync(0xffffffffu, s3, off);
                s4 += __shfl_xor_sync(0xffffffffu, s4, off);
                s5 += __shfl_xor_sync(0xffffffffu, s5, off);
            }
            if (lane == 0) {
                const float m   = s1 * (1.0f / DD);
                const float var = s2 * (1.0f / DD) - m * m;
                const float rs  = rsqrtf(var + 1e-5f);
                const float dot = rs * (s3 - m * s4) + s5 + c[p];
                alpha_s[r * PP + p] = 1.0f / (1.0f + __expf(-dot));
            }
        }
    }
    __syncthreads();

    // ---- scale u_hat by alpha in place (packed mul) ----
#pragma unroll
    for (int p = 0; p < PP; p++) {
#pragma unroll
        for (int r2 = 0; r2 < 8; r2++) {
            const ULL ap = pack2(alpha_s[(2 * r2) * PP + p], alpha_s[(2 * r2 + 1) * PP + p]);
            const int idx = (p * 8 + r2) * 256 + tid;
            u_ull[idx] = mul2(u_ull[idx], ap);
        }
    }
    __syncthreads();

    // ---- 2c: projection S = Z @ proj_W^T + proj_b (FFMA2) ----
    ULL acc2[8];
    {
        const float4* pw = (const float4*)(proj_W + (size_t)tid * COLS);
        const float pb = proj_b[tid];
#pragma unroll
        for (int r2 = 0; r2 < 8; r2++) acc2[r2] = pack2(pb, pb);

        for (int j4 = 0; j4 < 256; j4++) {
            const float4 w4 = pw[j4];
            const ULL w0 = pack2(w4.x, w4.x);
            const ULL w1 = pack2(w4.y, w4.y);
            const ULL w2 = pack2(w4.z, w4.z);
            const ULL w3 = pack2(w4.w, w4.w);
            const int p   = j4 >> 6;
            const int j4l = j4 & 63;
#pragma unroll
            for (int r2 = 0; r2 < 8; r2++) {
                const ULL* zp = u_ull + (p * 8 + r2) * 256 + j4l * 4;
                const ulonglong2 za = *(const ulonglong2*)(zp);
                const ulonglong2 zb = *(const ulonglong2*)(zp + 2);
                fma2(acc2[r2], za.x, w0);
                fma2(acc2[r2], za.y, w1);
                fma2(acc2[r2], zb.x, w2);
                fma2(acc2[r2], zb.y, w3);
            }
        }
    }

    // ---- final LayerNorm across D ----
    {
        float x[ROWS];
#pragma unroll
        for (int r2 = 0; r2 < 8; r2++) unpack2(acc2[r2], x[2 * r2], x[2 * r2 + 1]);

        const int wid = tid >> 5, lane = tid & 31;
#pragma unroll
        for (int r = 0; r < ROWS; r++) {
            float s1 = x[r];
            float s2 = x[r] * x[r];
#pragma unroll
            for (int off = 16; off; off >>= 1) {
                s1 += __shfl_xor_sync(0xffffffffu, s1, off);
                s2 += __shfl_xor_sync(0xffffffffu, s2, off);
            }
            if (lane == 0) {
                red_s[(r * 8 + wid) * 2 + 0] = s1;
                red_s[(r * 8 + wid) * 2 + 1] = s2;
            }
        }
        __syncthreads();
        const float og = out_g[tid], ob = out_b[tid];
#pragma unroll
        for (int r = 0; r < ROWS; r++) {
            float s1 = 0.f, s2 = 0.f;
#pragma unroll
            for (int w = 0; w < 8; w++) {
                s1 += red_s[(r * 8 + w) * 2 + 0];
                s2 += red_s[(r * 8 + w) * 2 + 1];
            }
            const float m   = s1 * (1.0f / DD);
            const float var = s2 * (1.0f / DD) - m * m;
            const float rs  = rsqrtf(var + 1e-5f);
            out[(size_t)(bt0 + r) * DD + tid] = (x[r] - m) * rs * og + ob;
        }
    }
}

extern "C" void kernel_launch(void* const* d_in, const int* in_sizes, int n_in,
                              void* d_out, int out_size)
{
    (void)in_sizes; (void)n_in; (void)out_size;
    const float* E_S    = (const float*)d_in[0];
    const float* W      = (const float*)d_in[1];
    const int*   pidx   = (const int*)  d_in[2];
    const float* part_W = (const float*)d_in[3];
    const float* part_b = (const float*)d_in[4];
    const float* v      = (const float*)d_in[5];
    const float* c      = (const float*)d_in[6];
    const float* ln_g   = (const float*)d_in[7];
    const float* ln_b   = (const float*)d_in[8];
    const float* proj_W = (const float*)d_in[9];
    const float* proj_b = (const float*)d_in[10];
    const float* out_g  = (const float*)d_in[11];
    const float* out_b  = (const float*)d_in[12];
    float* out = (float*)d_out;

    fs_phase1<<<BT / 2, 256>>>(E_S, W, pidx);

    cudaFuncSetAttribute(fs_phase2, cudaFuncAttributeMaxDynamicSharedMemorySize, SMEMB_BYTES);
    fs_phase2<<<BT / ROWS, THREADS, SMEMB_BYTES>>>(
        part_W, part_b, v, c, ln_g, ln_b,
        proj_W, proj_b, out_g, out_b, out);
}